// round 11
// baseline (speedup 1.0000x reference)
#include <cuda_runtime.h>
#include <cuda_fp16.h>
#include <math.h>

#define D 128
#define CLS 10
#define GMAX 512
#define NMAX 100096
#define EMAX 1700000
#define BN_EPS 1e-5f
#define AGG_BLOCKS 1184
#define POOL_BLOCKS 296
#define GEMM_SMEM (2 * 128 * 136 * 2)   // two fp16 tiles, stride 136

// ---------------- scratch (no allocation allowed) ----------------
__device__ __half g_bufh[(size_t)NMAX * D];   // GEMM output H (fp16, gathered)
__device__ __half g_buf1h[(size_t)NMAX * D];  // aggregation output (fp16)
__device__ __half g_wt[3 * D * D];            // fp16 transposed weights [n][k]
__device__ float  g_dinv[NMAX];
__device__ float  g_statsA[2 * D];
__device__ float  g_statsB[2 * D];
__device__ float  g_pooled[GMAX * D];
__device__ float  g_cnt[GMAX];

struct __align__(8) Edge { int s; float w; };
__device__ int   g_rowptr[NMAX + 1];
__device__ int   g_cursor[NMAX];
__device__ Edge  g_edge[EMAX];
__device__ int   g_blocksum[160];

// ---------------- prep: zero scratch + convert/transpose weights ----------------
__global__ void k_prep(int n, const float* __restrict__ w1, const float* __restrict__ w2,
                       const float* __restrict__ w3) {
    int i = blockIdx.x * blockDim.x + threadIdx.x;
    if (i < n) g_cursor[i] = 0;
    if (i < GMAX * D) g_pooled[i] = 0.0f;
    if (i < GMAX) g_cnt[i] = 0.0f;
    if (i < 2 * D) { g_statsA[i] = 0.0f; g_statsB[i] = 0.0f; }
    if (i < 3 * D * D) {
        int which = i >> 14;
        const float* w = (which == 0) ? w1 : (which == 1) ? w2 : w3;
        int idx = i & (D * D - 1);
        int k = idx >> 7, nn = idx & 127;
        g_wt[which * D * D + nn * D + k] = __float2half(w[k * D + nn]);
    }
}

__global__ void k_count(const int* __restrict__ ei, int E) {
    int e = blockIdx.x * blockDim.x + threadIdx.x;
    if (e < E) atomicAdd(&g_cursor[ei[E + e]], 1);
}

// ---------------- scanA: per-1024 local exclusive scan + block total + dinv ----------------
__global__ void k_scanA(int n) {
    __shared__ int wsum[8];
    int t = threadIdx.x;
    int base = blockIdx.x * 1024 + t * 4;
    int v[4];
#pragma unroll
    for (int j = 0; j < 4; j++) {
        v[j] = (base + j < n) ? g_cursor[base + j] : 0;
        if (base + j < n) g_dinv[base + j] = rsqrtf((float)(v[j] + 1));
    }
    int local = v[0] + v[1] + v[2] + v[3];
    int lane = t & 31, w = t >> 5;
    int x = local;
#pragma unroll
    for (int o = 1; o < 32; o <<= 1) {
        int y = __shfl_up_sync(0xffffffffu, x, o);
        if (lane >= o) x += y;
    }
    if (lane == 31) wsum[w] = x;
    __syncthreads();
    if (t == 0) {
        int acc = 0;
#pragma unroll
        for (int i = 0; i < 8; i++) { int tmp = wsum[i]; wsum[i] = acc; acc += tmp; }
    }
    __syncthreads();
    int run = x - local + wsum[w];
    if (t == 255) g_blocksum[blockIdx.x] = run + local;
#pragma unroll
    for (int j = 0; j < 4; j++) {
        if (base + j < n) g_rowptr[base + j] = run;
        run += v[j];
    }
}

// ---------------- scanC: add block-prefix (computed per-block) + copy to cursor ----------------
__global__ void k_scanC(int n, int E) {
    __shared__ int soff;
    int t = threadIdx.x;
    if (t == 0) {
        int acc = 0;
        int lim = blockIdx.x >> 2;   // 256-elem block -> 1024-elem scanA block index
        for (int i = 0; i < lim; i++) acc += g_blocksum[i];
        soff = acc;
    }
    __syncthreads();
    int i = blockIdx.x * 256 + t;
    if (i < n) {
        int v = g_rowptr[i] + soff;
        g_rowptr[i] = v;
        g_cursor[i] = v;
    }
    if (blockIdx.x == 0 && t == 0) g_rowptr[n] = E;
}

__global__ void k_fill(const int* __restrict__ ei, int E) {
    int e = blockIdx.x * blockDim.x + threadIdx.x;
    if (e >= E) return;
    int s = ei[e];
    int d = ei[E + e];
    int pos = atomicAdd(&g_cursor[d], 1);
    Edge ed;
    ed.s = s;
    ed.w = g_dinv[s] * g_dinv[d];
    g_edge[pos] = ed;
}

// ---------------- tensor-core GEMM: Hh[M,128] = bnrelu?(A[M,128]) @ W ----------------
// T = float (raw input) or __half. Wt fp16 [n][k]; mma m16n8k16 fp32 accum.
template<typename T, bool BNA>
__global__ __launch_bounds__(256) void k_gemm_tc(const T* __restrict__ A,
                                                 const __half* __restrict__ Wt,
                                                 __half* __restrict__ Hh,
                                                 const float* __restrict__ gam,
                                                 const float* __restrict__ bet,
                                                 float invn, int M) {
    extern __shared__ __half sm[];
    __half* sA = sm;                 // [128][136]
    __half* sB = sm + 128 * 136;     // [128][136]
    __shared__ float ssc[128], ssh[128];

    int tid = threadIdx.x;
    int m0 = blockIdx.x * 128;

    if (BNA) {
        if (tid < 128) {
            float mean = g_statsA[tid] * invn;
            float var = g_statsA[128 + tid] * invn - mean * mean;
            float sc = rsqrtf(var + BN_EPS) * gam[tid];
            ssc[tid] = sc;
            ssh[tid] = bet[tid] - mean * sc;
        }
        __syncthreads();
    }

    // load A tile: thread covers 8 contiguous elements of one row
#pragma unroll
    for (int i = 0; i < 8; i++) {
        int idx = tid + i * 256;
        int r = idx >> 4;
        int c8 = (idx & 15) << 3;
        if (sizeof(T) == 2 && !BNA) {
            uint4 u = make_uint4(0u, 0u, 0u, 0u);
            if (m0 + r < M) u = *(const uint4*)((const __half*)A + (size_t)(m0 + r) * 128 + c8);
            *(uint4*)(sA + r * 136 + c8) = u;
        } else {
            float f[8];
            if (m0 + r < M) {
                if (sizeof(T) == 4) {
                    const float* ap = (const float*)A + (size_t)(m0 + r) * 128 + c8;
                    float4 a0 = *(const float4*)(ap);
                    float4 a1 = *(const float4*)(ap + 4);
                    f[0] = a0.x; f[1] = a0.y; f[2] = a0.z; f[3] = a0.w;
                    f[4] = a1.x; f[5] = a1.y; f[6] = a1.z; f[7] = a1.w;
                } else {
                    uint4 u = *(const uint4*)((const __half*)A + (size_t)(m0 + r) * 128 + c8);
                    __half2* hp = (__half2*)&u;
#pragma unroll
                    for (int j = 0; j < 4; j++) {
                        float2 v = __half22float2(hp[j]);
                        f[j * 2] = v.x; f[j * 2 + 1] = v.y;
                    }
                }
            } else {
#pragma unroll
                for (int j = 0; j < 8; j++) f[j] = 0.f;
            }
            if (BNA) {
#pragma unroll
                for (int j = 0; j < 8; j++)
                    f[j] = fmaxf(fmaf(f[j], ssc[c8 + j], ssh[c8 + j]), 0.f);
            }
            __half2 h0 = __floats2half2_rn(f[0], f[1]);
            __half2 h1 = __floats2half2_rn(f[2], f[3]);
            __half2 h2 = __floats2half2_rn(f[4], f[5]);
            __half2 h3 = __floats2half2_rn(f[6], f[7]);
            uint4 u = make_uint4(*(unsigned*)&h0, *(unsigned*)&h1,
                                 *(unsigned*)&h2, *(unsigned*)&h3);
            *(uint4*)(sA + r * 136 + c8) = u;
        }
    }
    // load W tile
#pragma unroll
    for (int i = 0; i < 8; i++) {
        int idx = tid + i * 256;
        int r = idx >> 4;
        int c8 = (idx & 15) << 3;
        *(uint4*)(sB + r * 136 + c8) = *(const uint4*)(Wt + r * 128 + c8);
    }
    __syncthreads();

    int w = tid >> 5, lane = tid & 31;
    int g = lane >> 2, tg = lane & 3;
    int wm = (w >> 2) * 64;
    int wn = (w & 3) * 32;

    float acc[4][4][4];
#pragma unroll
    for (int mi = 0; mi < 4; mi++)
#pragma unroll
        for (int ni = 0; ni < 4; ni++)
#pragma unroll
            for (int j = 0; j < 4; j++) acc[mi][ni][j] = 0.f;

#pragma unroll
    for (int k0 = 0; k0 < 128; k0 += 16) {
        unsigned af[4][4], bf[4][2];
#pragma unroll
        for (int mi = 0; mi < 4; mi++) {
            const __half* base = sA + (wm + mi * 16 + g) * 136 + k0 + tg * 2;
            af[mi][0] = *(const unsigned*)(base);
            af[mi][1] = *(const unsigned*)(base + 8 * 136);
            af[mi][2] = *(const unsigned*)(base + 8);
            af[mi][3] = *(const unsigned*)(base + 8 * 136 + 8);
        }
#pragma unroll
        for (int ni = 0; ni < 4; ni++) {
            const __half* base = sB + (wn + ni * 8 + g) * 136 + k0 + tg * 2;
            bf[ni][0] = *(const unsigned*)(base);
            bf[ni][1] = *(const unsigned*)(base + 8);
        }
#pragma unroll
        for (int mi = 0; mi < 4; mi++)
#pragma unroll
            for (int ni = 0; ni < 4; ni++) {
                asm volatile(
                    "mma.sync.aligned.m16n8k16.row.col.f32.f16.f16.f32 "
                    "{%0,%1,%2,%3}, {%4,%5,%6,%7}, {%8,%9}, {%0,%1,%2,%3};"
                    : "+f"(acc[mi][ni][0]), "+f"(acc[mi][ni][1]),
                      "+f"(acc[mi][ni][2]), "+f"(acc[mi][ni][3])
                    : "r"(af[mi][0]), "r"(af[mi][1]), "r"(af[mi][2]), "r"(af[mi][3]),
                      "r"(bf[ni][0]), "r"(bf[ni][1]));
            }
    }

#pragma unroll
    for (int mi = 0; mi < 4; mi++) {
        int r0 = m0 + wm + mi * 16 + g;
        int r1 = r0 + 8;
#pragma unroll
        for (int ni = 0; ni < 4; ni++) {
            int c = wn + ni * 8 + tg * 2;
            if (r0 < M) {
                __half2 h = __floats2half2_rn(acc[mi][ni][0], acc[mi][ni][1]);
                *(__half2*)(Hh + (size_t)r0 * 128 + c) = h;
            }
            if (r1 < M) {
                __half2 h = __floats2half2_rn(acc[mi][ni][2], acc[mi][ni][3]);
                *(__half2*)(Hh + (size_t)r1 * 128 + c) = h;
            }
        }
    }
}

// ---------------- gather-aggregate + bias + relu (+ optional BN stats) ----------------
#define GATHER1(E0, ACC) do {                                                    \
    uint2 rr = *(const uint2*)(Hh + (size_t)(E0).s * 128 + lane * 4);            \
    float2 pa = __half22float2(*(__half2*)&rr.x);                                \
    float2 pb = __half22float2(*(__half2*)&rr.y);                                \
    (ACC).x = fmaf(pa.x, (E0).w, (ACC).x); (ACC).y = fmaf(pa.y, (E0).w, (ACC).y);\
    (ACC).z = fmaf(pb.x, (E0).w, (ACC).z); (ACC).w = fmaf(pb.y, (E0).w, (ACC).w);\
} while (0)

template<bool STATS>
__global__ __launch_bounds__(256) void k_aggregate(const __half* __restrict__ Hh,
                                                   __half* __restrict__ Outh,
                                                   const float* __restrict__ bias,
                                                   float* __restrict__ stats,
                                                   int n) {
    int lane = threadIdx.x & 31;
    int gw = blockIdx.x * 8 + (threadIdx.x >> 5);
    int totalW = gridDim.x * 8;

    const float4 bb = *(const float4*)(bias + lane * 4);
    float s[4] = {0.f, 0.f, 0.f, 0.f};
    float s2[4] = {0.f, 0.f, 0.f, 0.f};

    for (int row = gw; row < n; row += totalW) {
        float di = g_dinv[row];
        float sf = di * di;
        uint2 rs = *(const uint2*)(Hh + (size_t)row * 128 + lane * 4);
        float2 a0 = __half22float2(*(__half2*)&rs.x);
        float2 a1 = __half22float2(*(__half2*)&rs.y);
        float4 acc = make_float4(a0.x * sf, a0.y * sf, a1.x * sf, a1.y * sf);

        int p = g_rowptr[row];
        int pe = g_rowptr[row + 1];

        for (; p + 4 <= pe; p += 4) {
            Edge e0 = g_edge[p];
            Edge e1 = g_edge[p + 1];
            Edge e2 = g_edge[p + 2];
            Edge e3 = g_edge[p + 3];
            uint2 r0 = *(const uint2*)(Hh + (size_t)e0.s * 128 + lane * 4);
            uint2 r1 = *(const uint2*)(Hh + (size_t)e1.s * 128 + lane * 4);
            uint2 r2 = *(const uint2*)(Hh + (size_t)e2.s * 128 + lane * 4);
            uint2 r3 = *(const uint2*)(Hh + (size_t)e3.s * 128 + lane * 4);
            float2 v0a = __half22float2(*(__half2*)&r0.x);
            float2 v0b = __half22float2(*(__half2*)&r0.y);
            float2 v1a = __half22float2(*(__half2*)&r1.x);
            float2 v1b = __half22float2(*(__half2*)&r1.y);
            float2 v2a = __half22float2(*(__half2*)&r2.x);
            float2 v2b = __half22float2(*(__half2*)&r2.y);
            float2 v3a = __half22float2(*(__half2*)&r3.x);
            float2 v3b = __half22float2(*(__half2*)&r3.y);
            acc.x = fmaf(v0a.x, e0.w, acc.x); acc.y = fmaf(v0a.y, e0.w, acc.y);
            acc.z = fmaf(v0b.x, e0.w, acc.z); acc.w = fmaf(v0b.y, e0.w, acc.w);
            acc.x = fmaf(v1a.x, e1.w, acc.x); acc.y = fmaf(v1a.y, e1.w, acc.y);
            acc.z = fmaf(v1b.x, e1.w, acc.z); acc.w = fmaf(v1b.y, e1.w, acc.w);
            acc.x = fmaf(v2a.x, e2.w, acc.x); acc.y = fmaf(v2a.y, e2.w, acc.y);
            acc.z = fmaf(v2b.x, e2.w, acc.z); acc.w = fmaf(v2b.y, e2.w, acc.w);
            acc.x = fmaf(v3a.x, e3.w, acc.x); acc.y = fmaf(v3a.y, e3.w, acc.y);
            acc.z = fmaf(v3b.x, e3.w, acc.z); acc.w = fmaf(v3b.y, e3.w, acc.w);
        }
        for (; p < pe; p++) {
            Edge e0 = g_edge[p];
            GATHER1(e0, acc);
        }

        acc.x = fmaxf(acc.x + bb.x, 0.f);
        acc.y = fmaxf(acc.y + bb.y, 0.f);
        acc.z = fmaxf(acc.z + bb.z, 0.f);
        acc.w = fmaxf(acc.w + bb.w, 0.f);

        __half2 o0 = __floats2half2_rn(acc.x, acc.y);
        __half2 o1 = __floats2half2_rn(acc.z, acc.w);
        *(uint2*)(Outh + (size_t)row * 128 + lane * 4) =
            make_uint2(*(unsigned*)&o0, *(unsigned*)&o1);

        if (STATS) {
            s[0] += acc.x; s2[0] += acc.x * acc.x;
            s[1] += acc.y; s2[1] += acc.y * acc.y;
            s[2] += acc.z; s2[2] += acc.z * acc.z;
            s[3] += acc.w; s2[3] += acc.w * acc.w;
        }
    }

    if (STATS) {
        __shared__ float sh[256];
        sh[threadIdx.x] = 0.f;
        __syncthreads();
#pragma unroll
        for (int j = 0; j < 4; j++) {
            atomicAdd(&sh[lane * 4 + j], s[j]);
            atomicAdd(&sh[128 + lane * 4 + j], s2[j]);
        }
        __syncthreads();
        atomicAdd(&stats[threadIdx.x], sh[threadIdx.x]);
    }
}

// ---------------- pool (segmented) + fused BN2+relu (scale/shift computed in-block) ----------------
__global__ __launch_bounds__(256) void k_pool(const __half* __restrict__ Xh,
                                              const int* __restrict__ batch,
                                              const float* __restrict__ gam,
                                              const float* __restrict__ bet,
                                              float invn, int n) {
    __shared__ float ssc[128], ssh[128];
    int t = threadIdx.x;
    if (t < 128) {
        float mean = g_statsB[t] * invn;
        float var = g_statsB[128 + t] * invn - mean * mean;
        float sc = rsqrtf(var + BN_EPS) * gam[t];
        ssc[t] = sc;
        ssh[t] = bet[t] - mean * sc;
    }
    __syncthreads();

    int lane = t & 31;
    int w = blockIdx.x * 8 + (t >> 5);
    int totalW = gridDim.x * 8;
    int chunk = (n + totalW - 1) / totalW;
    int r0 = w * chunk;
    int r1 = min(r0 + chunk, n);
    if (r0 >= n) return;

    float4 sc = *(float4*)&ssc[lane * 4];
    float4 sh = *(float4*)&ssh[lane * 4];

    int curg = batch[r0];
    float4 acc = make_float4(0.f, 0.f, 0.f, 0.f);
    float c = 0.f;
    for (int r = r0; r < r1; r++) {
        int g = batch[r];
        if (g != curg) {
            float* o = g_pooled + (size_t)curg * 128 + lane * 4;
            atomicAdd(o + 0, acc.x); atomicAdd(o + 1, acc.y);
            atomicAdd(o + 2, acc.z); atomicAdd(o + 3, acc.w);
            if (lane == 0) atomicAdd(&g_cnt[curg], c);
            acc = make_float4(0.f, 0.f, 0.f, 0.f);
            c = 0.f;
            curg = g;
        }
        uint2 rv = *(const uint2*)(Xh + (size_t)r * 128 + lane * 4);
        float2 va = __half22float2(*(__half2*)&rv.x);
        float2 vb = __half22float2(*(__half2*)&rv.y);
        acc.x += fmaxf(fmaf(va.x, sc.x, sh.x), 0.f);
        acc.y += fmaxf(fmaf(va.y, sc.y, sh.y), 0.f);
        acc.z += fmaxf(fmaf(vb.x, sc.z, sh.z), 0.f);
        acc.w += fmaxf(fmaf(vb.y, sc.w, sh.w), 0.f);
        c += 1.f;
    }
    float* o = g_pooled + (size_t)curg * 128 + lane * 4;
    atomicAdd(o + 0, acc.x); atomicAdd(o + 1, acc.y);
    atomicAdd(o + 2, acc.z); atomicAdd(o + 3, acc.w);
    if (lane == 0) atomicAdd(&g_cnt[curg], c);
}

// ---------------- FC + log_softmax ----------------
__global__ void k_fc(const float* __restrict__ fcw, const float* __restrict__ fcb,
                     float* __restrict__ out) {
    int g = blockIdx.x;
    int c = threadIdx.x;
    __shared__ float lg[CLS];
    float inv = 1.0f / fmaxf(g_cnt[g], 1.0f);
    if (c < CLS) {
        float a = fcb[c];
        for (int k = 0; k < 128; k++)
            a = fmaf(g_pooled[(size_t)g * 128 + k] * inv, fcw[k * CLS + c], a);
        lg[c] = a;
    }
    __syncthreads();
    if (c < CLS) {
        float mx = -1e30f;
#pragma unroll
        for (int j = 0; j < CLS; j++) mx = fmaxf(mx, lg[j]);
        float se = 0.f;
#pragma unroll
        for (int j = 0; j < CLS; j++) se += expf(lg[j] - mx);
        out[(size_t)g * CLS + c] = lg[c] - mx - logf(se);
    }
}

// ---------------- host launch ----------------
extern "C" void kernel_launch(void* const* d_in, const int* in_sizes, int n_in,
                              void* d_out, int out_size) {
    const float* x = (const float*)d_in[0];
    const int* ei = (const int*)d_in[1];
    const int* batch = (const int*)d_in[2];
    const float* w1 = (const float*)d_in[3];
    const float* b1 = (const float*)d_in[4];
    const float* w2 = (const float*)d_in[5];
    const float* b2 = (const float*)d_in[6];
    const float* w3 = (const float*)d_in[7];
    const float* b3 = (const float*)d_in[8];
    const float* g1 = (const float*)d_in[9];
    const float* be1 = (const float*)d_in[10];
    const float* g2 = (const float*)d_in[11];
    const float* be2 = (const float*)d_in[12];
    const float* fcw = (const float*)d_in[13];
    const float* fcb = (const float*)d_in[14];
    float* out = (float*)d_out;

    int n = in_sizes[0] / D;
    int E = in_sizes[1] / 2;

    __half *bufh, *buf1h, *wt;
    float *stA, *stB;
    cudaGetSymbolAddress((void**)&bufh, g_bufh);
    cudaGetSymbolAddress((void**)&buf1h, g_buf1h);
    cudaGetSymbolAddress((void**)&wt, g_wt);
    cudaGetSymbolAddress((void**)&stA, g_statsA);
    cudaGetSymbolAddress((void**)&stB, g_statsB);

    cudaFuncSetAttribute(k_gemm_tc<float, false>, cudaFuncAttributeMaxDynamicSharedMemorySize, GEMM_SMEM);
    cudaFuncSetAttribute(k_gemm_tc<__half, false>, cudaFuncAttributeMaxDynamicSharedMemorySize, GEMM_SMEM);
    cudaFuncSetAttribute(k_gemm_tc<__half, true>, cudaFuncAttributeMaxDynamicSharedMemorySize, GEMM_SMEM);

    int initCov = (n > GMAX * D) ? n : GMAX * D;
    int nb = (n + 1023) / 1024;

    // ---- CSR build + weight conversion (6 launches) ----
    k_prep<<<(initCov + 255) / 256, 256>>>(n, w1, w2, w3);
    k_count<<<(E + 255) / 256, 256>>>(ei, E);
    k_scanA<<<nb, 256>>>(n);
    k_scanC<<<(n + 255) / 256, 256>>>(n, E);
    k_fill<<<(E + 255) / 256, 256>>>(ei, E);

    int gemmBlocks = (n + 127) / 128;
    float invn = 1.0f / (float)n;

    // ---- layer 1 (fp32 input converted in GEMM) ----
    k_gemm_tc<float, false><<<gemmBlocks, 256, GEMM_SMEM>>>(x, wt, bufh, nullptr, nullptr, 0.f, n);
    k_aggregate<false><<<AGG_BLOCKS, 256>>>(bufh, buf1h, b1, nullptr, n);

    // ---- layer 2 (stats for bn1 fused) ----
    k_gemm_tc<__half, false><<<gemmBlocks, 256, GEMM_SMEM>>>(buf1h, wt + D * D, bufh, nullptr, nullptr, 0.f, n);
    k_aggregate<true><<<AGG_BLOCKS, 256>>>(bufh, buf1h, b2, stA, n);

    // ---- layer 3 (bn1+relu computed+fused in GEMM A-load; stats for bn2 fused) ----
    k_gemm_tc<__half, true><<<gemmBlocks, 256, GEMM_SMEM>>>(buf1h, wt + 2 * D * D, bufh, g1, be1, invn, n);
    k_aggregate<true><<<AGG_BLOCKS, 256>>>(bufh, buf1h, b3, stB, n);

    // ---- pool (bn2 computed+fused) + fc + log_softmax ----
    k_pool<<<POOL_BLOCKS, 256>>>(buf1h, batch, g2, be2, invn, n);
    k_fc<<<GMAX, 32>>>(fcw, fcb, out);
}

// round 13
// speedup vs baseline: 1.0481x; 1.0481x over previous
#include <cuda_runtime.h>
#include <cuda_fp16.h>
#include <math.h>

#define D 128
#define CLS 10
#define GMAX 512
#define NMAX 100096          // 782 * 128, exact tile multiple
#define EMAX 1700000
#define BN_EPS 1e-5f
#define AGG_BLOCKS 1184
#define POOL_BLOCKS 296
#define GEMM_BLOCKS 296
#define TILE_HALFS (128 * 136)
#define GEMM_SMEM (3 * TILE_HALFS * 2)   // W + double-buffered A, fp16

// ---------------- scratch (no allocation allowed) ----------------
__device__ __half g_bufx[(size_t)NMAX * D];   // fp16 copy of input x
__device__ __half g_bufh[(size_t)NMAX * D];   // GEMM output H (fp16, gathered)
__device__ __half g_buf1h[(size_t)NMAX * D];  // aggregation output (fp16)
__device__ __half g_wt[3 * D * D];            // fp16 transposed weights [n][k]
__device__ float  g_dinv[NMAX];
__device__ float  g_statsA[2 * D];
__device__ float  g_statsB[2 * D];
__device__ float  g_pooled[GMAX * D];
__device__ float  g_cnt[GMAX];

struct __align__(8) Edge { int s; float w; };
__device__ int   g_rowptr[NMAX + 1];
__device__ int   g_cursor[NMAX];
__device__ Edge  g_edge[EMAX];
__device__ int   g_blocksum[160];

// ---------------- prep: zero scratch + convert/transpose weights ----------------
__global__ void k_prep(int n, const float* __restrict__ w1, const float* __restrict__ w2,
                       const float* __restrict__ w3) {
    int i = blockIdx.x * blockDim.x + threadIdx.x;
    if (i < n) g_cursor[i] = 0;
    if (i < GMAX * D) g_pooled[i] = 0.0f;
    if (i < GMAX) g_cnt[i] = 0.0f;
    if (i < 2 * D) { g_statsA[i] = 0.0f; g_statsB[i] = 0.0f; }
    if (i < 3 * D * D) {
        int which = i >> 14;
        const float* w = (which == 0) ? w1 : (which == 1) ? w2 : w3;
        int idx = i & (D * D - 1);
        int k = idx >> 7, nn = idx & 127;
        g_wt[which * D * D + nn * D + k] = __float2half(w[k * D + nn]);
    }
}

__global__ void k_count(const int* __restrict__ ei, int E) {
    int e = blockIdx.x * blockDim.x + threadIdx.x;
    if (e < E) atomicAdd(&g_cursor[ei[E + e]], 1);
}

// ---------------- scanA: per-1024 local exclusive scan + block total + dinv ----------------
__global__ void k_scanA(int n) {
    __shared__ int wsum[8];
    int t = threadIdx.x;
    int base = blockIdx.x * 1024 + t * 4;
    int v[4];
#pragma unroll
    for (int j = 0; j < 4; j++) {
        v[j] = (base + j < n) ? g_cursor[base + j] : 0;
        if (base + j < n) g_dinv[base + j] = rsqrtf((float)(v[j] + 1));
    }
    int local = v[0] + v[1] + v[2] + v[3];
    int lane = t & 31, w = t >> 5;
    int x = local;
#pragma unroll
    for (int o = 1; o < 32; o <<= 1) {
        int y = __shfl_up_sync(0xffffffffu, x, o);
        if (lane >= o) x += y;
    }
    if (lane == 31) wsum[w] = x;
    __syncthreads();
    if (t == 0) {
        int acc = 0;
#pragma unroll
        for (int i = 0; i < 8; i++) { int tmp = wsum[i]; wsum[i] = acc; acc += tmp; }
    }
    __syncthreads();
    int run = x - local + wsum[w];
    if (t == 255) g_blocksum[blockIdx.x] = run + local;
#pragma unroll
    for (int j = 0; j < 4; j++) {
        if (base + j < n) g_rowptr[base + j] = run;
        run += v[j];
    }
}

__global__ void k_scanB(int nb) {
    __shared__ int s[160];
    int t = threadIdx.x;
    if (t < nb) s[t] = g_blocksum[t];
    __syncthreads();
    if (t == 0) {
        int acc = 0;
        for (int i = 0; i < nb; i++) { int tmp = s[i]; s[i] = acc; acc += tmp; }
    }
    __syncthreads();
    if (t < nb) g_blocksum[t] = s[t];
}

__global__ void k_scanC(int n, int E) {
    int i = blockIdx.x * blockDim.x + threadIdx.x;
    if (i < n) {
        int v = g_rowptr[i] + g_blocksum[i >> 10];
        g_rowptr[i] = v;
        g_cursor[i] = v;
    }
    if (i == 0) g_rowptr[n] = E;
}

__global__ void k_fill(const int* __restrict__ ei, int E) {
    int e = blockIdx.x * blockDim.x + threadIdx.x;
    if (e >= E) return;
    int s = ei[e];
    int d = ei[E + e];
    int pos = atomicAdd(&g_cursor[d], 1);
    Edge ed;
    ed.s = s;
    ed.w = g_dinv[s] * g_dinv[d];
    g_edge[pos] = ed;
}

// ---------------- x -> fp16 ----------------
__global__ void k_xconv(const float* __restrict__ x, __half* __restrict__ xh, int n) {
    int i = blockIdx.x * blockDim.x + threadIdx.x;  // over n*32 float4s
    if (i < n * 32) {
        float4 v = *(const float4*)(x + (size_t)i * 4);
        __half2 h0 = __floats2half2_rn(v.x, v.y);
        __half2 h1 = __floats2half2_rn(v.z, v.w);
        *(uint2*)(xh + (size_t)i * 4) = make_uint2(*(unsigned*)&h0, *(unsigned*)&h1);
    }
}

// ---------------- persistent pipelined tensor-core GEMM ----------------
// Hh[tile range] = bnrelu?(A) @ W.  A fp16 row-major (NMAX-padded), Wt fp16 [n][k].
// W loaded once per block; A tiles double-buffered via cp.async.
__device__ __forceinline__ void cp_async16(void* sdst, const void* gsrc) {
    unsigned saddr = (unsigned)__cvta_generic_to_shared(sdst);
    asm volatile("cp.async.ca.shared.global [%0], [%1], 16;" :: "r"(saddr), "l"(gsrc));
}

template<bool BNA>
__global__ __launch_bounds__(256) void k_gemm_p(const __half* __restrict__ A,
                                                const __half* __restrict__ Wt,
                                                __half* __restrict__ Hh,
                                                const float* __restrict__ gam,
                                                const float* __restrict__ bet,
                                                float invn, int numTiles) {
    extern __shared__ __half sm[];
    __half* sW = sm;                         // [128][136]
    __half* sAbuf = sm + TILE_HALFS;         // 2 x [128][136]
    __shared__ float ssc[128], ssh[128];

    int tid = threadIdx.x;

    if (BNA) {
        if (tid < 128) {
            float mean = g_statsA[tid] * invn;
            float var = g_statsA[128 + tid] * invn - mean * mean;
            float sc = rsqrtf(var + BN_EPS) * gam[tid];
            ssc[tid] = sc;
            ssh[tid] = bet[tid] - mean * sc;
        }
        __syncthreads();
    }

    // load W once
#pragma unroll
    for (int i = 0; i < 8; i++) {
        int idx = tid + i * 256;
        int r = idx >> 4;
        int c8 = (idx & 15) << 3;
        *(uint4*)(sW + r * 136 + c8) = *(const uint4*)(Wt + r * 128 + c8);
    }

    int w = tid >> 5, lane = tid & 31;
    int g = lane >> 2, tg = lane & 3;
    int wm = (w >> 2) * 64;
    int wn = (w & 3) * 32;

    // prefetch first tile
    int tile = blockIdx.x;
    if (tile < numTiles) {
        const __half* base = A + (size_t)tile * 128 * 128;
        __half* sb = sAbuf;
#pragma unroll
        for (int i = 0; i < 8; i++) {
            int idx = tid + i * 256;
            int r = idx >> 4;
            int c8 = (idx & 15) << 3;
            cp_async16(sb + r * 136 + c8, base + r * 128 + c8);
        }
        asm volatile("cp.async.commit_group;");
    }

    int buf = 0;
    for (; tile < numTiles; tile += gridDim.x) {
        int next = tile + gridDim.x;
        if (next < numTiles) {
            const __half* base = A + (size_t)next * 128 * 128;
            __half* sb = sAbuf + (buf ^ 1) * TILE_HALFS;
#pragma unroll
            for (int i = 0; i < 8; i++) {
                int idx = tid + i * 256;
                int r = idx >> 4;
                int c8 = (idx & 15) << 3;
                cp_async16(sb + r * 136 + c8, base + r * 128 + c8);
            }
            asm volatile("cp.async.commit_group;");
            asm volatile("cp.async.wait_group 1;");
        } else {
            asm volatile("cp.async.wait_group 0;");
        }
        __syncthreads();

        __half* sA = sAbuf + buf * TILE_HALFS;

        if (BNA) {
            // in-place BN affine + relu on the arrived tile
#pragma unroll
            for (int i = 0; i < 8; i++) {
                int idx = tid + i * 256;
                int r = idx >> 4;
                int c8 = (idx & 15) << 3;
                uint4 u = *(uint4*)(sA + r * 136 + c8);
                __half2* hp = (__half2*)&u;
#pragma unroll
                for (int j = 0; j < 4; j++) {
                    float2 v = __half22float2(hp[j]);
                    int c = c8 + j * 2;
                    v.x = fmaxf(fmaf(v.x, ssc[c], ssh[c]), 0.f);
                    v.y = fmaxf(fmaf(v.y, ssc[c + 1], ssh[c + 1]), 0.f);
                    hp[j] = __floats2half2_rn(v.x, v.y);
                }
                *(uint4*)(sA + r * 136 + c8) = u;
            }
            __syncthreads();
        }

        float acc[4][4][4];
#pragma unroll
        for (int mi = 0; mi < 4; mi++)
#pragma unroll
            for (int ni = 0; ni < 4; ni++)
#pragma unroll
                for (int j = 0; j < 4; j++) acc[mi][ni][j] = 0.f;

#pragma unroll
        for (int k0 = 0; k0 < 128; k0 += 16) {
            unsigned af[4][4], bf[4][2];
#pragma unroll
            for (int mi = 0; mi < 4; mi++) {
                const __half* base = sA + (wm + mi * 16 + g) * 136 + k0 + tg * 2;
                af[mi][0] = *(const unsigned*)(base);
                af[mi][1] = *(const unsigned*)(base + 8 * 136);
                af[mi][2] = *(const unsigned*)(base + 8);
                af[mi][3] = *(const unsigned*)(base + 8 * 136 + 8);
            }
#pragma unroll
            for (int ni = 0; ni < 4; ni++) {
                const __half* base = sW + (wn + ni * 8 + g) * 136 + k0 + tg * 2;
                bf[ni][0] = *(const unsigned*)(base);
                bf[ni][1] = *(const unsigned*)(base + 8);
            }
#pragma unroll
            for (int mi = 0; mi < 4; mi++)
#pragma unroll
                for (int ni = 0; ni < 4; ni++) {
                    asm volatile(
                        "mma.sync.aligned.m16n8k16.row.col.f32.f16.f16.f32 "
                        "{%0,%1,%2,%3}, {%4,%5,%6,%7}, {%8,%9}, {%0,%1,%2,%3};"
                        : "+f"(acc[mi][ni][0]), "+f"(acc[mi][ni][1]),
                          "+f"(acc[mi][ni][2]), "+f"(acc[mi][ni][3])
                        : "r"(af[mi][0]), "r"(af[mi][1]), "r"(af[mi][2]), "r"(af[mi][3]),
                          "r"(bf[ni][0]), "r"(bf[ni][1]));
                }
        }

        int m0 = tile * 128;
#pragma unroll
        for (int mi = 0; mi < 4; mi++) {
            int r0 = m0 + wm + mi * 16 + g;
            int r1 = r0 + 8;
#pragma unroll
            for (int ni = 0; ni < 4; ni++) {
                int c = wn + ni * 8 + tg * 2;
                __half2 h0 = __floats2half2_rn(acc[mi][ni][0], acc[mi][ni][1]);
                __half2 h1 = __floats2half2_rn(acc[mi][ni][2], acc[mi][ni][3]);
                *(__half2*)(Hh + (size_t)r0 * 128 + c) = h0;
                *(__half2*)(Hh + (size_t)r1 * 128 + c) = h1;
            }
        }
        __syncthreads();   // all reads of sA[buf] done before next issue overwrites it
        buf ^= 1;
    }
}

// ---------------- gather-aggregate + bias + relu (+ optional BN stats) ----------------
template<bool STATS>
__global__ __launch_bounds__(256) void k_aggregate(const __half* __restrict__ Hh,
                                                   __half* __restrict__ Outh,
                                                   const float* __restrict__ bias,
                                                   float* __restrict__ stats,
                                                   int n) {
    int lane = threadIdx.x & 31;
    int gw = blockIdx.x * 8 + (threadIdx.x >> 5);
    int totalW = gridDim.x * 8;

    const float4 bb = *(const float4*)(bias + lane * 4);
    float s[4] = {0.f, 0.f, 0.f, 0.f};
    float s2[4] = {0.f, 0.f, 0.f, 0.f};

    for (int row = gw; row < n; row += totalW) {
        float di = g_dinv[row];
        float sf = di * di;
        uint2 rs = *(const uint2*)(Hh + (size_t)row * 128 + lane * 4);
        float2 a0 = __half22float2(*(__half2*)&rs.x);
        float2 a1 = __half22float2(*(__half2*)&rs.y);
        float4 acc = make_float4(a0.x * sf, a0.y * sf, a1.x * sf, a1.y * sf);

        int p = g_rowptr[row];
        int pe = g_rowptr[row + 1];

        for (; p + 2 <= pe; p += 2) {
            Edge e0 = g_edge[p];
            Edge e1 = g_edge[p + 1];
            uint2 r0 = *(const uint2*)(Hh + (size_t)e0.s * 128 + lane * 4);
            uint2 r1 = *(const uint2*)(Hh + (size_t)e1.s * 128 + lane * 4);
            float2 v0a = __half22float2(*(__half2*)&r0.x);
            float2 v0b = __half22float2(*(__half2*)&r0.y);
            float2 v1a = __half22float2(*(__half2*)&r1.x);
            float2 v1b = __half22float2(*(__half2*)&r1.y);
            acc.x = fmaf(v0a.x, e0.w, acc.x); acc.y = fmaf(v0a.y, e0.w, acc.y);
            acc.z = fmaf(v0b.x, e0.w, acc.z); acc.w = fmaf(v0b.y, e0.w, acc.w);
            acc.x = fmaf(v1a.x, e1.w, acc.x); acc.y = fmaf(v1a.y, e1.w, acc.y);
            acc.z = fmaf(v1b.x, e1.w, acc.z); acc.w = fmaf(v1b.y, e1.w, acc.w);
        }
        if (p < pe) {
            Edge e0 = g_edge[p];
            uint2 r0 = *(const uint2*)(Hh + (size_t)e0.s * 128 + lane * 4);
            float2 v0a = __half22float2(*(__half2*)&r0.x);
            float2 v0b = __half22float2(*(__half2*)&r0.y);
            acc.x = fmaf(v0a.x, e0.w, acc.x); acc.y = fmaf(v0a.y, e0.w, acc.y);
            acc.z = fmaf(v0b.x, e0.w, acc.z); acc.w = fmaf(v0b.y, e0.w, acc.w);
        }

        acc.x = fmaxf(acc.x + bb.x, 0.f);
        acc.y = fmaxf(acc.y + bb.y, 0.f);
        acc.z = fmaxf(acc.z + bb.z, 0.f);
        acc.w = fmaxf(acc.w + bb.w, 0.f);

        __half2 o0 = __floats2half2_rn(acc.x, acc.y);
        __half2 o1 = __floats2half2_rn(acc.z, acc.w);
        *(uint2*)(Outh + (size_t)row * 128 + lane * 4) =
            make_uint2(*(unsigned*)&o0, *(unsigned*)&o1);

        if (STATS) {
            s[0] += acc.x; s2[0] += acc.x * acc.x;
            s[1] += acc.y; s2[1] += acc.y * acc.y;
            s[2] += acc.z; s2[2] += acc.z * acc.z;
            s[3] += acc.w; s2[3] += acc.w * acc.w;
        }
    }

    if (STATS) {
        __shared__ float sh[256];
        sh[threadIdx.x] = 0.f;
        __syncthreads();
#pragma unroll
        for (int j = 0; j < 4; j++) {
            atomicAdd(&sh[lane * 4 + j], s[j]);
            atomicAdd(&sh[128 + lane * 4 + j], s2[j]);
        }
        __syncthreads();
        atomicAdd(&stats[threadIdx.x], sh[threadIdx.x]);
    }
}

// ---------------- pool (segmented) + fused BN2+relu (scale/shift computed in-block) ----------------
__global__ __launch_bounds__(256) void k_pool(const __half* __restrict__ Xh,
                                              const int* __restrict__ batch,
                                              const float* __restrict__ gam,
                                              const float* __restrict__ bet,
                                              float invn, int n) {
    __shared__ float ssc[128], ssh[128];
    int t = threadIdx.x;
    if (t < 128) {
        float mean = g_statsB[t] * invn;
        float var = g_statsB[128 + t] * invn - mean * mean;
        float sc = rsqrtf(var + BN_EPS) * gam[t];
        ssc[t] = sc;
        ssh[t] = bet[t] - mean * sc;
    }
    __syncthreads();

    int lane = t & 31;
    int w = blockIdx.x * 8 + (t >> 5);
    int totalW = gridDim.x * 8;
    int chunk = (n + totalW - 1) / totalW;
    int r0 = w * chunk;
    int r1 = min(r0 + chunk, n);
    if (r0 >= n) return;

    float4 sc = *(float4*)&ssc[lane * 4];
    float4 sh = *(float4*)&ssh[lane * 4];

    int curg = batch[r0];
    float4 acc = make_float4(0.f, 0.f, 0.f, 0.f);
    float c = 0.f;
    for (int r = r0; r < r1; r++) {
        int g = batch[r];
        if (g != curg) {
            float* o = g_pooled + (size_t)curg * 128 + lane * 4;
            atomicAdd(o + 0, acc.x); atomicAdd(o + 1, acc.y);
            atomicAdd(o + 2, acc.z); atomicAdd(o + 3, acc.w);
            if (lane == 0) atomicAdd(&g_cnt[curg], c);
            acc = make_float4(0.f, 0.f, 0.f, 0.f);
            c = 0.f;
            curg = g;
        }
        uint2 rv = *(const uint2*)(Xh + (size_t)r * 128 + lane * 4);
        float2 va = __half22float2(*(__half2*)&rv.x);
        float2 vb = __half22float2(*(__half2*)&rv.y);
        acc.x += fmaxf(fmaf(va.x, sc.x, sh.x), 0.f);
        acc.y += fmaxf(fmaf(va.y, sc.y, sh.y), 0.f);
        acc.z += fmaxf(fmaf(vb.x, sc.z, sh.z), 0.f);
        acc.w += fmaxf(fmaf(vb.y, sc.w, sh.w), 0.f);
        c += 1.f;
    }
    float* o = g_pooled + (size_t)curg * 128 + lane * 4;
    atomicAdd(o + 0, acc.x); atomicAdd(o + 1, acc.y);
    atomicAdd(o + 2, acc.z); atomicAdd(o + 3, acc.w);
    if (lane == 0) atomicAdd(&g_cnt[curg], c);
}

// ---------------- FC + log_softmax ----------------
__global__ void k_fc(const float* __restrict__ fcw, const float* __restrict__ fcb,
                     float* __restrict__ out) {
    int g = blockIdx.x;
    int c = threadIdx.x;
    __shared__ float lg[CLS];
    float inv = 1.0f / fmaxf(g_cnt[g], 1.0f);
    if (c < CLS) {
        float a = fcb[c];
        for (int k = 0; k < 128; k++)
            a = fmaf(g_pooled[(size_t)g * 128 + k] * inv, fcw[k * CLS + c], a);
        lg[c] = a;
    }
    __syncthreads();
    if (c < CLS) {
        float mx = -1e30f;
#pragma unroll
        for (int j = 0; j < CLS; j++) mx = fmaxf(mx, lg[j]);
        float se = 0.f;
#pragma unroll
        for (int j = 0; j < CLS; j++) se += expf(lg[j] - mx);
        out[(size_t)g * CLS + c] = lg[c] - mx - logf(se);
    }
}

// ---------------- host launch ----------------
extern "C" void kernel_launch(void* const* d_in, const int* in_sizes, int n_in,
                              void* d_out, int out_size) {
    const float* x = (const float*)d_in[0];
    const int* ei = (const int*)d_in[1];
    const int* batch = (const int*)d_in[2];
    const float* w1 = (const float*)d_in[3];
    const float* b1 = (const float*)d_in[4];
    const float* w2 = (const float*)d_in[5];
    const float* b2 = (const float*)d_in[6];
    const float* w3 = (const float*)d_in[7];
    const float* b3 = (const float*)d_in[8];
    const float* g1 = (const float*)d_in[9];
    const float* be1 = (const float*)d_in[10];
    const float* g2 = (const float*)d_in[11];
    const float* be2 = (const float*)d_in[12];
    const float* fcw = (const float*)d_in[13];
    const float* fcb = (const float*)d_in[14];
    float* out = (float*)d_out;

    int n = in_sizes[0] / D;
    int E = in_sizes[1] / 2;

    __half *bufx, *bufh, *buf1h, *wt;
    float *stA, *stB;
    cudaGetSymbolAddress((void**)&bufx, g_bufx);
    cudaGetSymbolAddress((void**)&bufh, g_bufh);
    cudaGetSymbolAddress((void**)&buf1h, g_buf1h);
    cudaGetSymbolAddress((void**)&wt, g_wt);
    cudaGetSymbolAddress((void**)&stA, g_statsA);
    cudaGetSymbolAddress((void**)&stB, g_statsB);

    cudaFuncSetAttribute(k_gemm_p<false>, cudaFuncAttributeMaxDynamicSharedMemorySize, GEMM_SMEM);
    cudaFuncSetAttribute(k_gemm_p<true>, cudaFuncAttributeMaxDynamicSharedMemorySize, GEMM_SMEM);

    int initCov = (n > GMAX * D) ? n : GMAX * D;
    int nb = (n + 1023) / 1024;
    int numTiles = (n + 127) / 128;
    float invn = 1.0f / (float)n;

    // ---- CSR build + conversions ----
    k_prep<<<(initCov + 255) / 256, 256>>>(n, w1, w2, w3);
    k_count<<<(E + 255) / 256, 256>>>(ei, E);
    k_scanA<<<nb, 256>>>(n);
    k_scanB<<<1, 160>>>(nb);
    k_scanC<<<(n + 255) / 256, 256>>>(n, E);
    k_fill<<<(E + 255) / 256, 256>>>(ei, E);
    k_xconv<<<(n * 32 + 255) / 256, 256>>>(x, bufx, n);

    // ---- layer 1 ----
    k_gemm_p<false><<<GEMM_BLOCKS, 256, GEMM_SMEM>>>(bufx, wt, bufh, nullptr, nullptr, 0.f, numTiles);
    k_aggregate<false><<<AGG_BLOCKS, 256>>>(bufh, buf1h, b1, nullptr, n);

    // ---- layer 2 (stats for bn1 fused) ----
    k_gemm_p<false><<<GEMM_BLOCKS, 256, GEMM_SMEM>>>(buf1h, wt + D * D, bufh, nullptr, nullptr, 0.f, numTiles);
    k_aggregate<true><<<AGG_BLOCKS, 256>>>(bufh, buf1h, b2, stA, n);

    // ---- layer 3 (bn1+relu applied in-smem in GEMM; stats for bn2 fused) ----
    k_gemm_p<true><<<GEMM_BLOCKS, 256, GEMM_SMEM>>>(buf1h, wt + 2 * D * D, bufh, g1, be1, invn, n >= 0 ? numTiles : 0);
    k_aggregate<true><<<AGG_BLOCKS, 256>>>(bufh, buf1h, b3, stB, n);

    // ---- pool (bn2 computed+fused) + fc + log_softmax ----
    k_pool<<<POOL_BLOCKS, 256>>>(buf1h, batch, g2, be2, invn, n);
    k_fc<<<GMAX, 32>>>(fcw, fcb, out);
}

// round 16
// speedup vs baseline: 1.0645x; 1.0157x over previous
#include <cuda_runtime.h>
#include <cuda_fp16.h>
#include <math.h>

#define D 128
#define CLS 10
#define GMAX 512
#define NMAX 100096          // 782 * 128, exact tile multiple
#define EMAX 1700000
#define BN_EPS 1e-5f
#define AGG_BLOCKS 1184
#define POOL_BLOCKS 296
#define GEMM_BLOCKS 296
#define TILE_HALFS (128 * 136)
#define GEMM_SMEM (3 * TILE_HALFS * 2)   // W + double-buffered A, fp16

// ---------------- scratch (no allocation allowed) ----------------
__device__ __half g_bufx[(size_t)NMAX * D];   // fp16 copy of input x
__device__ __half g_bufh[(size_t)NMAX * D];   // GEMM output H (fp16, gathered)
__device__ __half g_buf1h[(size_t)NMAX * D];  // aggregation output (fp16)
__device__ __half g_wt[3 * D * D];            // fp16 transposed weights [n][k]
__device__ float  g_dinv[NMAX];
__device__ float  g_statsA[2 * D];
__device__ float  g_statsB[2 * D];
__device__ float  g_pooled[GMAX * D];
__device__ float  g_cnt[GMAX];

struct __align__(8) Edge { int s; float w; };
__device__ int   g_rowptr[NMAX + 1];
__device__ int   g_cursor[NMAX];
__device__ Edge  g_edge[EMAX];
__device__ int   g_blocksum[160];

// ---------------- prep: zero scratch + convert/transpose weights ----------------
__global__ void k_prep(int n, const float* __restrict__ w1, const float* __restrict__ w2,
                       const float* __restrict__ w3) {
    int i = blockIdx.x * blockDim.x + threadIdx.x;
    if (i < n) g_cursor[i] = 0;
    if (i < GMAX * D) g_pooled[i] = 0.0f;
    if (i < GMAX) g_cnt[i] = 0.0f;
    if (i < 2 * D) { g_statsA[i] = 0.0f; g_statsB[i] = 0.0f; }
    if (i < 3 * D * D) {
        int which = i >> 14;
        const float* w = (which == 0) ? w1 : (which == 1) ? w2 : w3;
        int idx = i & (D * D - 1);
        int k = idx >> 7, nn = idx & 127;
        g_wt[which * D * D + nn * D + k] = __float2half(w[k * D + nn]);
    }
}

// ---------------- count in-degree + x->fp16 conversion (independent, one launch) ----------------
__global__ void k_count_xc(const int* __restrict__ ei, int E,
                           const float* __restrict__ x, __half* __restrict__ xh, int nq) {
    int i = blockIdx.x * blockDim.x + threadIdx.x;
    if (i < E) atomicAdd(&g_cursor[ei[E + i]], 1);
    if (i < nq) {  // nq = n*32 float4s
        float4 v = *(const float4*)(x + (size_t)i * 4);
        __half2 h0 = __floats2half2_rn(v.x, v.y);
        __half2 h1 = __floats2half2_rn(v.z, v.w);
        *(uint2*)(xh + (size_t)i * 4) = make_uint2(*(unsigned*)&h0, *(unsigned*)&h1);
    }
}

// ---------------- scanA: per-1024 local exclusive scan + block total + dinv ----------------
__global__ void k_scanA(int n) {
    __shared__ int wsum[8];
    int t = threadIdx.x;
    int base = blockIdx.x * 1024 + t * 4;
    int v[4];
#pragma unroll
    for (int j = 0; j < 4; j++) {
        v[j] = (base + j < n) ? g_cursor[base + j] : 0;
        if (base + j < n) g_dinv[base + j] = rsqrtf((float)(v[j] + 1));
    }
    int local = v[0] + v[1] + v[2] + v[3];
    int lane = t & 31, w = t >> 5;
    int x = local;
#pragma unroll
    for (int o = 1; o < 32; o <<= 1) {
        int y = __shfl_up_sync(0xffffffffu, x, o);
        if (lane >= o) x += y;
    }
    if (lane == 31) wsum[w] = x;
    __syncthreads();
    if (t == 0) {
        int acc = 0;
#pragma unroll
        for (int i = 0; i < 8; i++) { int tmp = wsum[i]; wsum[i] = acc; acc += tmp; }
    }
    __syncthreads();
    int run = x - local + wsum[w];
    if (t == 255) g_blocksum[blockIdx.x] = run + local;
#pragma unroll
    for (int j = 0; j < 4; j++) {
        if (base + j < n) g_rowptr[base + j] = run;
        run += v[j];
    }
}

// ---------------- scanC: parallel-reduce block prefix + finalize rowptr/cursor ----------------
__global__ void k_scanC(int n, int E) {
    __shared__ int red[256];
    int t = threadIdx.x;
    int lim = blockIdx.x >> 2;   // number of full scanA(1024) blocks before this 256-range
    red[t] = (t < lim) ? g_blocksum[t] : 0;
    __syncthreads();
#pragma unroll
    for (int o = 128; o > 0; o >>= 1) {
        if (t < o) red[t] += red[t + o];
        __syncthreads();
    }
    int soff = red[0];
    int i = blockIdx.x * 256 + t;
    if (i < n) {
        int v = g_rowptr[i] + soff;
        g_rowptr[i] = v;
        g_cursor[i] = v;
    }
    if (i == 0) g_rowptr[n] = E;
}

__global__ void k_fill(const int* __restrict__ ei, int E) {
    int e = blockIdx.x * blockDim.x + threadIdx.x;
    if (e >= E) return;
    int s = ei[e];
    int d = ei[E + e];
    int pos = atomicAdd(&g_cursor[d], 1);
    Edge ed;
    ed.s = s;
    ed.w = g_dinv[s] * g_dinv[d];
    g_edge[pos] = ed;
}

// ---------------- persistent pipelined tensor-core GEMM ----------------
__device__ __forceinline__ void cp_async16(void* sdst, const void* gsrc) {
    unsigned saddr = (unsigned)__cvta_generic_to_shared(sdst);
    asm volatile("cp.async.ca.shared.global [%0], [%1], 16;" :: "r"(saddr), "l"(gsrc));
}

template<bool BNA>
__global__ __launch_bounds__(256) void k_gemm_p(const __half* __restrict__ A,
                                                const __half* __restrict__ Wt,
                                                __half* __restrict__ Hh,
                                                const float* __restrict__ gam,
                                                const float* __restrict__ bet,
                                                float invn, int numTiles) {
    extern __shared__ __half sm[];
    __half* sW = sm;                         // [128][136]
    __half* sAbuf = sm + TILE_HALFS;         // 2 x [128][136]
    __shared__ float ssc[128], ssh[128];

    int tid = threadIdx.x;

    if (BNA) {
        if (tid < 128) {
            float mean = g_statsA[tid] * invn;
            float var = g_statsA[128 + tid] * invn - mean * mean;
            float sc = rsqrtf(var + BN_EPS) * gam[tid];
            ssc[tid] = sc;
            ssh[tid] = bet[tid] - mean * sc;
        }
        __syncthreads();
    }

    // load W once
#pragma unroll
    for (int i = 0; i < 8; i++) {
        int idx = tid + i * 256;
        int r = idx >> 4;
        int c8 = (idx & 15) << 3;
        *(uint4*)(sW + r * 136 + c8) = *(const uint4*)(Wt + r * 128 + c8);
    }

    int w = tid >> 5, lane = tid & 31;
    int g = lane >> 2, tg = lane & 3;
    int wm = (w >> 2) * 64;
    int wn = (w & 3) * 32;

    // prefetch first tile
    int tile = blockIdx.x;
    if (tile < numTiles) {
        const __half* base = A + (size_t)tile * 128 * 128;
        __half* sb = sAbuf;
#pragma unroll
        for (int i = 0; i < 8; i++) {
            int idx = tid + i * 256;
            int r = idx >> 4;
            int c8 = (idx & 15) << 3;
            cp_async16(sb + r * 136 + c8, base + r * 128 + c8);
        }
        asm volatile("cp.async.commit_group;");
    }

    int buf = 0;
    for (; tile < numTiles; tile += gridDim.x) {
        int next = tile + gridDim.x;
        if (next < numTiles) {
            const __half* base = A + (size_t)next * 128 * 128;
            __half* sb = sAbuf + (buf ^ 1) * TILE_HALFS;
#pragma unroll
            for (int i = 0; i < 8; i++) {
                int idx = tid + i * 256;
                int r = idx >> 4;
                int c8 = (idx & 15) << 3;
                cp_async16(sb + r * 136 + c8, base + r * 128 + c8);
            }
            asm volatile("cp.async.commit_group;");
            asm volatile("cp.async.wait_group 1;");
        } else {
            asm volatile("cp.async.wait_group 0;");
        }
        __syncthreads();

        __half* sA = sAbuf + buf * TILE_HALFS;

        if (BNA) {
#pragma unroll
            for (int i = 0; i < 8; i++) {
                int idx = tid + i * 256;
                int r = idx >> 4;
                int c8 = (idx & 15) << 3;
                uint4 u = *(uint4*)(sA + r * 136 + c8);
                __half2* hp = (__half2*)&u;
#pragma unroll
                for (int j = 0; j < 4; j++) {
                    float2 v = __half22float2(hp[j]);
                    int c = c8 + j * 2;
                    v.x = fmaxf(fmaf(v.x, ssc[c], ssh[c]), 0.f);
                    v.y = fmaxf(fmaf(v.y, ssc[c + 1], ssh[c + 1]), 0.f);
                    hp[j] = __floats2half2_rn(v.x, v.y);
                }
                *(uint4*)(sA + r * 136 + c8) = u;
            }
            __syncthreads();
        }

        float acc[4][4][4];
#pragma unroll
        for (int mi = 0; mi < 4; mi++)
#pragma unroll
            for (int ni = 0; ni < 4; ni++)
#pragma unroll
                for (int j = 0; j < 4; j++) acc[mi][ni][j] = 0.f;

#pragma unroll
        for (int k0 = 0; k0 < 128; k0 += 16) {
            unsigned af[4][4], bf[4][2];
#pragma unroll
            for (int mi = 0; mi < 4; mi++) {
                const __half* base = sA + (wm + mi * 16 + g) * 136 + k0 + tg * 2;
                af[mi][0] = *(const unsigned*)(base);
                af[mi][1] = *(const unsigned*)(base + 8 * 136);
                af[mi][2] = *(const unsigned*)(base + 8);
                af[mi][3] = *(const unsigned*)(base + 8 * 136 + 8);
            }
#pragma unroll
            for (int ni = 0; ni < 4; ni++) {
                const __half* base = sW + (wn + ni * 8 + g) * 136 + k0 + tg * 2;
                bf[ni][0] = *(const unsigned*)(base);
                bf[ni][1] = *(const unsigned*)(base + 8);
            }
#pragma unroll
            for (int mi = 0; mi < 4; mi++)
#pragma unroll
                for (int ni = 0; ni < 4; ni++) {
                    asm volatile(
                        "mma.sync.aligned.m16n8k16.row.col.f32.f16.f16.f32 "
                        "{%0,%1,%2,%3}, {%4,%5,%6,%7}, {%8,%9}, {%0,%1,%2,%3};"
                        : "+f"(acc[mi][ni][0]), "+f"(acc[mi][ni][1]),
                          "+f"(acc[mi][ni][2]), "+f"(acc[mi][ni][3])
                        : "r"(af[mi][0]), "r"(af[mi][1]), "r"(af[mi][2]), "r"(af[mi][3]),
                          "r"(bf[ni][0]), "r"(bf[ni][1]));
                }
        }

        int m0 = tile * 128;
#pragma unroll
        for (int mi = 0; mi < 4; mi++) {
            int r0 = m0 + wm + mi * 16 + g;
            int r1 = r0 + 8;
#pragma unroll
            for (int ni = 0; ni < 4; ni++) {
                int c = wn + ni * 8 + tg * 2;
                __half2 h0 = __floats2half2_rn(acc[mi][ni][0], acc[mi][ni][1]);
                __half2 h1 = __floats2half2_rn(acc[mi][ni][2], acc[mi][ni][3]);
                *(__half2*)(Hh + (size_t)r0 * 128 + c) = h0;
                *(__half2*)(Hh + (size_t)r1 * 128 + c) = h1;
            }
        }
        __syncthreads();
        buf ^= 1;
    }
}

// ---------------- gather-aggregate + bias + relu (+ optional BN stats) ----------------
template<bool STATS>
__global__ __launch_bounds__(256) void k_aggregate(const __half* __restrict__ Hh,
                                                   __half* __restrict__ Outh,
                                                   const float* __restrict__ bias,
                                                   float* __restrict__ stats,
                                                   int n) {
    int lane = threadIdx.x & 31;
    int gw = blockIdx.x * 8 + (threadIdx.x >> 5);
    int totalW = gridDim.x * 8;

    const float4 bb = *(const float4*)(bias + lane * 4);
    float s[4] = {0.f, 0.f, 0.f, 0.f};
    float s2[4] = {0.f, 0.f, 0.f, 0.f};

    for (int row = gw; row < n; row += totalW) {
        float di = g_dinv[row];
        float sf = di * di;
        uint2 rs = *(const uint2*)(Hh + (size_t)row * 128 + lane * 4);
        float2 a0 = __half22float2(*(__half2*)&rs.x);
        float2 a1 = __half22float2(*(__half2*)&rs.y);
        float4 acc = make_float4(a0.x * sf, a0.y * sf, a1.x * sf, a1.y * sf);

        int p = g_rowptr[row];
        int pe = g_rowptr[row + 1];

        for (; p + 2 <= pe; p += 2) {
            Edge e0 = g_edge[p];
            Edge e1 = g_edge[p + 1];
            uint2 r0 = *(const uint2*)(Hh + (size_t)e0.s * 128 + lane * 4);
            uint2 r1 = *(const uint2*)(Hh + (size_t)e1.s * 128 + lane * 4);
            float2 v0a = __half22float2(*(__half2*)&r0.x);
            float2 v0b = __half22float2(*(__half2*)&r0.y);
            float2 v1a = __half22float2(*(__half2*)&r1.x);
            float2 v1b = __half22float2(*(__half2*)&r1.y);
            acc.x = fmaf(v0a.x, e0.w, acc.x); acc.y = fmaf(v0a.y, e0.w, acc.y);
            acc.z = fmaf(v0b.x, e0.w, acc.z); acc.w = fmaf(v0b.y, e0.w, acc.w);
            acc.x = fmaf(v1a.x, e1.w, acc.x); acc.y = fmaf(v1a.y, e1.w, acc.y);
            acc.z = fmaf(v1b.x, e1.w, acc.z); acc.w = fmaf(v1b.y, e1.w, acc.w);
        }
        if (p < pe) {
            Edge e0 = g_edge[p];
            uint2 r0 = *(const uint2*)(Hh + (size_t)e0.s * 128 + lane * 4);
            float2 v0a = __half22float2(*(__half2*)&r0.x);
            float2 v0b = __half22float2(*(__half2*)&r0.y);
            acc.x = fmaf(v0a.x, e0.w, acc.x); acc.y = fmaf(v0a.y, e0.w, acc.y);
            acc.z = fmaf(v0b.x, e0.w, acc.z); acc.w = fmaf(v0b.y, e0.w, acc.w);
        }

        acc.x = fmaxf(acc.x + bb.x, 0.f);
        acc.y = fmaxf(acc.y + bb.y, 0.f);
        acc.z = fmaxf(acc.z + bb.z, 0.f);
        acc.w = fmaxf(acc.w + bb.w, 0.f);

        __half2 o0 = __floats2half2_rn(acc.x, acc.y);
        __half2 o1 = __floats2half2_rn(acc.z, acc.w);
        *(uint2*)(Outh + (size_t)row * 128 + lane * 4) =
            make_uint2(*(unsigned*)&o0, *(unsigned*)&o1);

        if (STATS) {
            s[0] += acc.x; s2[0] += acc.x * acc.x;
            s[1] += acc.y; s2[1] += acc.y * acc.y;
            s[2] += acc.z; s2[2] += acc.z * acc.z;
            s[3] += acc.w; s2[3] += acc.w * acc.w;
        }
    }

    if (STATS) {
        __shared__ float sh[256];
        sh[threadIdx.x] = 0.f;
        __syncthreads();
#pragma unroll
        for (int j = 0; j < 4; j++) {
            atomicAdd(&sh[lane * 4 + j], s[j]);
            atomicAdd(&sh[128 + lane * 4 + j], s2[j]);
        }
        __syncthreads();
        atomicAdd(&stats[threadIdx.x], sh[threadIdx.x]);
    }
}

// ---------------- pool (segmented) + fused BN2+relu ----------------
__global__ __launch_bounds__(256) void k_pool(const __half* __restrict__ Xh,
                                              const int* __restrict__ batch,
                                              const float* __restrict__ gam,
                                              const float* __restrict__ bet,
                                              float invn, int n) {
    __shared__ float ssc[128], ssh[128];
    int t = threadIdx.x;
    if (t < 128) {
        float mean = g_statsB[t] * invn;
        float var = g_statsB[128 + t] * invn - mean * mean;
        float sc = rsqrtf(var + BN_EPS) * gam[t];
        ssc[t] = sc;
        ssh[t] = bet[t] - mean * sc;
    }
    __syncthreads();

    int lane = t & 31;
    int w = blockIdx.x * 8 + (t >> 5);
    int totalW = gridDim.x * 8;
    int chunk = (n + totalW - 1) / totalW;
    int r0 = w * chunk;
    int r1 = min(r0 + chunk, n);
    if (r0 >= n) return;

    float4 sc = *(float4*)&ssc[lane * 4];
    float4 sh = *(float4*)&ssh[lane * 4];

    int curg = batch[r0];
    float4 acc = make_float4(0.f, 0.f, 0.f, 0.f);
    float c = 0.f;
    for (int r = r0; r < r1; r++) {
        int g = batch[r];
        if (g != curg) {
            float* o = g_pooled + (size_t)curg * 128 + lane * 4;
            atomicAdd(o + 0, acc.x); atomicAdd(o + 1, acc.y);
            atomicAdd(o + 2, acc.z); atomicAdd(o + 3, acc.w);
            if (lane == 0) atomicAdd(&g_cnt[curg], c);
            acc = make_float4(0.f, 0.f, 0.f, 0.f);
            c = 0.f;
            curg = g;
        }
        uint2 rv = *(const uint2*)(Xh + (size_t)r * 128 + lane * 4);
        float2 va = __half22float2(*(__half2*)&rv.x);
        float2 vb = __half22float2(*(__half2*)&rv.y);
        acc.x += fmaxf(fmaf(va.x, sc.x, sh.x), 0.f);
        acc.y += fmaxf(fmaf(va.y, sc.y, sh.y), 0.f);
        acc.z += fmaxf(fmaf(vb.x, sc.z, sh.z), 0.f);
        acc.w += fmaxf(fmaf(vb.y, sc.w, sh.w), 0.f);
        c += 1.f;
    }
    float* o = g_pooled + (size_t)curg * 128 + lane * 4;
    atomicAdd(o + 0, acc.x); atomicAdd(o + 1, acc.y);
    atomicAdd(o + 2, acc.z); atomicAdd(o + 3, acc.w);
    if (lane == 0) atomicAdd(&g_cnt[curg], c);
}

// ---------------- FC + log_softmax ----------------
__global__ void k_fc(const float* __restrict__ fcw, const float* __restrict__ fcb,
                     float* __restrict__ out) {
    int g = blockIdx.x;
    int c = threadIdx.x;
    __shared__ float lg[CLS];
    float inv = 1.0f / fmaxf(g_cnt[g], 1.0f);
    if (c < CLS) {
        float a = fcb[c];
        for (int k = 0; k < 128; k++)
            a = fmaf(g_pooled[(size_t)g * 128 + k] * inv, fcw[k * CLS + c], a);
        lg[c] = a;
    }
    __syncthreads();
    if (c < CLS) {
        float mx = -1e30f;
#pragma unroll
        for (int j = 0; j < CLS; j++) mx = fmaxf(mx, lg[j]);
        float se = 0.f;
#pragma unroll
        for (int j = 0; j < CLS; j++) se += expf(lg[j] - mx);
        out[(size_t)g * CLS + c] = lg[c] - mx - logf(se);
    }
}

// ---------------- host launch ----------------
extern "C" void kernel_launch(void* const* d_in, const int* in_sizes, int n_in,
                              void* d_out, int out_size) {
    const float* x = (const float*)d_in[0];
    const int* ei = (const int*)d_in[1];
    const int* batch = (const int*)d_in[2];
    const float* w1 = (const float*)d_in[3];
    const float* b1 = (const float*)d_in[4];
    const float* w2 = (const float*)d_in[5];
    const float* b2 = (const float*)d_in[6];
    const float* w3 = (const float*)d_in[7];
    const float* b3 = (const float*)d_in[8];
    const float* g1 = (const float*)d_in[9];
    const float* be1 = (const float*)d_in[10];
    const float* g2 = (const float*)d_in[11];
    const float* be2 = (const float*)d_in[12];
    const float* fcw = (const float*)d_in[13];
    const float* fcb = (const float*)d_in[14];
    float* out = (float*)d_out;

    int n = in_sizes[0] / D;
    int E = in_sizes[1] / 2;

    __half *bufx, *bufh, *buf1h, *wt;
    float *stA, *stB;
    cudaGetSymbolAddress((void**)&bufx, g_bufx);
    cudaGetSymbolAddress((void**)&bufh, g_bufh);
    cudaGetSymbolAddress((void**)&buf1h, g_buf1h);
    cudaGetSymbolAddress((void**)&wt, g_wt);
    cudaGetSymbolAddress((void**)&stA, g_statsA);
    cudaGetSymbolAddress((void**)&stB, g_statsB);

    cudaFuncSetAttribute(k_gemm_p<false>, cudaFuncAttributeMaxDynamicSharedMemorySize, GEMM_SMEM);
    cudaFuncSetAttribute(k_gemm_p<true>, cudaFuncAttributeMaxDynamicSharedMemorySize, GEMM_SMEM);

    int initCov = (n > GMAX * D) ? n : GMAX * D;
    int nb = (n + 1023) / 1024;
    int nq = n * 32;                      // float4 count for x conversion
    int cxCov = (E > nq) ? E : nq;
    int numTiles = (n + 127) / 128;
    float invn = 1.0f / (float)n;

    // ---- CSR build + conversions (5 launches) ----
    k_prep<<<(initCov + 255) / 256, 256>>>(n, w1, w2, w3);
    k_count_xc<<<(cxCov + 255) / 256, 256>>>(ei, E, x, bufx, nq);
    k_scanA<<<nb, 256>>>(n);
    k_scanC<<<(n + 255) / 256, 256>>>(n, E);
    k_fill<<<(E + 255) / 256, 256>>>(ei, E);

    // ---- layer 1 ----
    k_gemm_p<false><<<GEMM_BLOCKS, 256, GEMM_SMEM>>>(bufx, wt, bufh, nullptr, nullptr, 0.f, numTiles);
    k_aggregate<false><<<AGG_BLOCKS, 256>>>(bufh, buf1h, b1, nullptr, n);

    // ---- layer 2 (stats for bn1 fused) ----
    k_gemm_p<false><<<GEMM_BLOCKS, 256, GEMM_SMEM>>>(buf1h, wt + D * D, bufh, nullptr, nullptr, 0.f, numTiles);
    k_aggregate<true><<<AGG_BLOCKS, 256>>>(bufh, buf1h, b2, stA, n);

    // ---- layer 3 (bn1+relu applied in-smem in GEMM; stats for bn2 fused) ----
    k_gemm_p<true><<<GEMM_BLOCKS, 256, GEMM_SMEM>>>(buf1h, wt + 2 * D * D, bufh, g1, be1, invn, numTiles);
    k_aggregate<true><<<AGG_BLOCKS, 256>>>(bufh, buf1h, b3, stB, n);

    // ---- pool (bn2 computed+fused) + fc + log_softmax ----
    k_pool<<<POOL_BLOCKS, 256>>>(buf1h, batch, g2, be2, invn, n);
    k_fc<<<GMAX, 32>>>(fcw, fcb, out);
}